// round 1
// baseline (speedup 1.0000x reference)
#include <cuda_runtime.h>
#include <math.h>

// ---------------- problem constants ----------------
#define BATCH 16
#define TT    24
#define NW    49
#define SEQ   (TT*NW)        // 1176
#define EMB   2048
#define HEADS 8
#define DHEAD 64
#define INNER 512            // HEADS*DHEAD
#define NLAT  256
#define LKV   (SEQ + NLAT)   // 1432
#define FFD   8192           // EMB*4
#define NDEPTH 3
#define EPSV  1e-5f
#define ATT_SCALE 0.125f     // DHEAD^-0.5

// ---------------- scratch (device globals; no allocation allowed) ----------------
__device__ float g_X1 [BATCH*SEQ*EMB];       // ln(x); reused as xm per depth
__device__ float g_Q  [BATCH*SEQ*INNER];
__device__ float g_KV [BATCH*SEQ*2*INNER];
__device__ float g_AO [BATCH*SEQ*INNER];
__device__ float g_X  [BATCH*SEQ*EMB];       // residual stream after stage A
__device__ float g_LAT[BATCH*NLAT*EMB];
__device__ float g_LM [BATCH*NLAT*EMB];      // ln(lat); reused as ff-norm input
__device__ float g_QL [BATCH*NLAT*INNER];
__device__ float g_KVA[BATCH*LKV*2*INNER];
__device__ float g_O  [BATCH*NLAT*INNER];
__device__ float g_H  [BATCH*NLAT*FFD];

// ---------------- LayerNorm: one block per row of 2048 ----------------
__global__ void __launch_bounds__(256) ln_kernel(
    const float* __restrict__ in, const float* __restrict__ sc,
    const float* __restrict__ bi, float* __restrict__ out)
{
    long r = blockIdx.x;
    const float* x = in + r*(long)EMB;
    float* y = out + r*(long)EMB;
    int tid = threadIdx.x;

    float4 va = ((const float4*)x)[tid];
    float4 vb = ((const float4*)x)[tid + 256];
    float sum = va.x+va.y+va.z+va.w + vb.x+vb.y+vb.z+vb.w;
    float sq  = va.x*va.x+va.y*va.y+va.z*va.z+va.w*va.w
              + vb.x*vb.x+vb.y*vb.y+vb.z*vb.z+vb.w*vb.w;
    #pragma unroll
    for (int o = 16; o > 0; o >>= 1) {
        sum += __shfl_down_sync(0xffffffffu, sum, o);
        sq  += __shfl_down_sync(0xffffffffu, sq, o);
    }
    __shared__ float rs[16];
    __shared__ float mb[2];
    int w = tid >> 5, lane = tid & 31;
    if (!lane) { rs[w] = sum; rs[8 + w] = sq; }
    __syncthreads();
    if (tid == 0) {
        float s = 0.f, q = 0.f;
        #pragma unroll
        for (int i = 0; i < 8; i++) { s += rs[i]; q += rs[8 + i]; }
        float mean = s * (1.0f / EMB);
        float var  = q * (1.0f / EMB) - mean * mean;
        mb[0] = mean; mb[1] = rsqrtf(var + EPSV);
    }
    __syncthreads();
    float mean = mb[0], rstd = mb[1];

    float4 sa = ((const float4*)sc)[tid], sb = ((const float4*)sc)[tid + 256];
    float4 ba = ((const float4*)bi)[tid], bb = ((const float4*)bi)[tid + 256];
    float4 oa, ob;
    oa.x = (va.x-mean)*rstd*sa.x + ba.x;  oa.y = (va.y-mean)*rstd*sa.y + ba.y;
    oa.z = (va.z-mean)*rstd*sa.z + ba.z;  oa.w = (va.w-mean)*rstd*sa.w + ba.w;
    ob.x = (vb.x-mean)*rstd*sb.x + bb.x;  ob.y = (vb.y-mean)*rstd*sb.y + bb.y;
    ob.z = (vb.z-mean)*rstd*sb.z + bb.z;  ob.w = (vb.w-mean)*rstd*sb.w + bb.w;
    ((float4*)y)[tid] = oa;
    ((float4*)y)[tid + 256] = ob;
}

// ---------------- SGEMM: C = op(A@B) (+addsrc), with batch-row remap on output ----------------
// A: MxK row-major, B: KxN row-major. M%128==0, N%128==0, K%8==0 (all shapes here satisfy this).
// output row mapping: gr -> (gr/in_rpb)*out_rpb + out_off + gr%in_rpb  (identity when in_rpb==out_rpb==1)
__global__ void __launch_bounds__(256) sgemm128(
    const float* __restrict__ A, const float* __restrict__ B, float* __restrict__ C,
    int M, int N, int K,
    const float* __restrict__ addsrc, int do_gelu,
    int in_rpb, int out_rpb, int out_off)
{
    __shared__ float As[8][128];
    __shared__ float Bs[8][128];

    int tid  = threadIdx.x;
    int row0 = blockIdx.y * 128;
    int col0 = blockIdx.x * 128;

    int a_r = tid >> 1;
    int a_c = (tid & 1) * 4;
    int b_r = tid >> 5;
    int b_c = (tid & 31) * 4;

    const float* Ap = A + (long)(row0 + a_r) * K + a_c;
    const float* Bp = B + (long)b_r * N + col0 + b_c;

    int tr = (tid >> 4) * 8;
    int tc = (tid & 15) * 8;

    float acc[8][8];
    #pragma unroll
    for (int i = 0; i < 8; i++)
        #pragma unroll
        for (int j = 0; j < 8; j++) acc[i][j] = 0.f;

    for (int k0 = 0; k0 < K; k0 += 8) {
        float4 av = *(const float4*)Ap;
        float4 bv = *(const float4*)Bp;
        __syncthreads();
        As[a_c + 0][a_r] = av.x;
        As[a_c + 1][a_r] = av.y;
        As[a_c + 2][a_r] = av.z;
        As[a_c + 3][a_r] = av.w;
        *(float4*)&Bs[b_r][b_c] = bv;
        __syncthreads();
        #pragma unroll
        for (int kk = 0; kk < 8; kk++) {
            float4 a0 = *(const float4*)&As[kk][tr];
            float4 a1 = *(const float4*)&As[kk][tr + 4];
            float4 b0 = *(const float4*)&Bs[kk][tc];
            float4 b1 = *(const float4*)&Bs[kk][tc + 4];
            float ra[8] = {a0.x,a0.y,a0.z,a0.w,a1.x,a1.y,a1.z,a1.w};
            float rb[8] = {b0.x,b0.y,b0.z,b0.w,b1.x,b1.y,b1.z,b1.w};
            #pragma unroll
            for (int i = 0; i < 8; i++)
                #pragma unroll
                for (int j = 0; j < 8; j++)
                    acc[i][j] += ra[i] * rb[j];
        }
        Ap += 8;
        Bp += (long)8 * N;
    }

    #pragma unroll
    for (int i = 0; i < 8; i++) {
        long gr = row0 + tr + i;
        long bb2 = gr / in_rpb;
        long orow = bb2 * out_rpb + out_off + (gr - bb2 * in_rpb);
        float* crow = C + orow * N + col0 + tc;
        const float* arow = addsrc ? (addsrc + orow * N + col0 + tc) : (const float*)0;
        float v[8];
        #pragma unroll
        for (int j = 0; j < 8; j++) {
            float t = acc[i][j];
            if (do_gelu) t = 0.5f * t * (1.0f + erff(t * 0.70710678118654752f));
            v[j] = t;
        }
        if (arow) {
            float4 d0 = *(const float4*)(arow);
            float4 d1 = *(const float4*)(arow + 4);
            v[0]+=d0.x; v[1]+=d0.y; v[2]+=d0.z; v[3]+=d0.w;
            v[4]+=d1.x; v[5]+=d1.y; v[6]+=d1.z; v[7]+=d1.w;
        }
        float4 o0 = make_float4(v[0],v[1],v[2],v[3]);
        float4 o1 = make_float4(v[4],v[5],v[6],v[7]);
        *(float4*)(crow)     = o0;
        *(float4*)(crow + 4) = o1;
    }
}

// ---------------- local attention: one block per (b,h,t), 49x49 ----------------
__global__ void __launch_bounds__(256) attn_local_kernel(
    const float* __restrict__ Q, const float* __restrict__ KV, float* __restrict__ O)
{
    __shared__ float qsT[DHEAD][NW];
    __shared__ float ksT[DHEAD][NW];
    __shared__ float sim[NW * NW];

    int g = blockIdx.x;             // b*HEADS*TT + h*TT + t
    int t = g % TT;
    int h = (g / TT) % HEADS;
    int b = g / (TT * HEADS);
    long base = (long)b * SEQ + (long)t * NW;
    int tid = threadIdx.x;

    for (int e = tid; e < NW * DHEAD; e += 256) {
        int i = e >> 6, d = e & 63;
        qsT[d][i] = Q [(base + i) * INNER     + h * DHEAD + d] * ATT_SCALE;
        ksT[d][i] = KV[(base + i) * (2*INNER) + h * DHEAD + d];
    }
    __syncthreads();

    for (int p = tid; p < NW * NW; p += 256) {
        int i = p / NW, j = p % NW;
        float s = 0.f;
        #pragma unroll
        for (int d = 0; d < DHEAD; d++) s += qsT[d][i] * ksT[d][j];
        sim[p] = s;
    }
    __syncthreads();

    if (tid < NW) {
        float m = -1e30f;
        for (int j = 0; j < NW; j++) m = fmaxf(m, sim[tid * NW + j]);
        float sum = 0.f;
        for (int j = 0; j < NW; j++) {
            float e = expf(sim[tid * NW + j] - m);
            sim[tid * NW + j] = e;
            sum += e;
        }
        float inv = 1.0f / sum;
        for (int j = 0; j < NW; j++) sim[tid * NW + j] *= inv;
    }
    __syncthreads();

    // reuse qsT as vT
    for (int e = tid; e < NW * DHEAD; e += 256) {
        int j = e >> 6, d = e & 63;
        qsT[d][j] = KV[(base + j) * (2*INNER) + INNER + h * DHEAD + d];
    }
    __syncthreads();

    for (int o = tid; o < NW * DHEAD; o += 256) {
        int i = o >> 6, d = o & 63;
        float acc = 0.f;
        for (int j = 0; j < NW; j++) acc += sim[i * NW + j] * qsT[d][j];
        O[(base + i) * INNER + h * DHEAD + d] = acc;
    }
}

// ---------------- latent cross-attention: streaming online softmax ----------------
// block = (b, h, 32-row q tile); 256 threads = 32 rows x 8 cols, 8 output dims/thread
__global__ void __launch_bounds__(256) attn_latent_kernel(
    const float* __restrict__ QL, const float* __restrict__ KVA, float* __restrict__ O)
{
    __shared__ float qsT[DHEAD][32];
    __shared__ float ksT[DHEAD][32];
    __shared__ float vs [32][DHEAD];

    int blk = blockIdx.x;           // b*64 + h*8 + qt
    int qt = blk & 7;
    int h  = (blk >> 3) & 7;
    int b  = blk >> 6;
    int q0 = qt * 32;
    int tid = threadIdx.x;
    int r = tid >> 3;               // row in tile 0..31
    int c = tid & 7;                // 0..7
    int d0 = c * 8;

    for (int e = tid; e < 32 * DHEAD; e += 256) {
        int i = e >> 6, d = e & 63;
        qsT[d][i] = QL[((long)b * NLAT + q0 + i) * INNER + h * DHEAD + d] * ATT_SCALE;
    }

    float outacc[8];
    #pragma unroll
    for (int dd = 0; dd < 8; dd++) outacc[dd] = 0.f;
    float rowmax = -1e30f, rowsum = 0.f;
    int lanebase = (tid & 31) & ~7;
    __syncthreads();

    for (int j0 = 0; j0 < LKV; j0 += 32) {
        int jn = LKV - j0; if (jn > 32) jn = 32;
        for (int e = tid; e < 32 * DHEAD; e += 256) {
            int j = e >> 6, d = e & 63;
            if (j < jn) {
                long row = (long)b * LKV + j0 + j;
                ksT[d][j] = KVA[row * (2*INNER)         + h * DHEAD + d];
                vs [j][d] = KVA[row * (2*INNER) + INNER + h * DHEAD + d];
            } else {
                ksT[d][j] = 0.f;
                vs [j][d] = 0.f;
            }
        }
        __syncthreads();

        float s[4];
        #pragma unroll
        for (int jj = 0; jj < 4; jj++) {
            int j = c * 4 + jj;
            float acc = 0.f;
            #pragma unroll
            for (int d = 0; d < DHEAD; d++) acc += qsT[d][r] * ksT[d][j];
            s[jj] = (j < jn) ? acc : -1e30f;
        }
        float cm = fmaxf(fmaxf(s[0], s[1]), fmaxf(s[2], s[3]));
        cm = fmaxf(cm, __shfl_xor_sync(0xffffffffu, cm, 1));
        cm = fmaxf(cm, __shfl_xor_sync(0xffffffffu, cm, 2));
        cm = fmaxf(cm, __shfl_xor_sync(0xffffffffu, cm, 4));
        float nm = fmaxf(rowmax, cm);
        float corr = expf(rowmax - nm);
        float p[4], ps = 0.f;
        #pragma unroll
        for (int jj = 0; jj < 4; jj++) { p[jj] = expf(s[jj] - nm); ps += p[jj]; }
        ps += __shfl_xor_sync(0xffffffffu, ps, 1);
        ps += __shfl_xor_sync(0xffffffffu, ps, 2);
        ps += __shfl_xor_sync(0xffffffffu, ps, 4);
        rowsum = rowsum * corr + ps;
        rowmax = nm;
        #pragma unroll
        for (int dd = 0; dd < 8; dd++) outacc[dd] *= corr;

        #pragma unroll
        for (int jc = 0; jc < 8; jc++) {
            #pragma unroll
            for (int jj = 0; jj < 4; jj++) {
                float pj = __shfl_sync(0xffffffffu, p[jj], lanebase + jc);
                int j = jc * 4 + jj;
                #pragma unroll
                for (int dd = 0; dd < 8; dd++)
                    outacc[dd] += pj * vs[j][d0 + dd];
            }
        }
        __syncthreads();
    }

    float inv = 1.0f / rowsum;
    float* op = O + ((long)b * NLAT + q0 + r) * INNER + h * DHEAD + d0;
    #pragma unroll
    for (int dd = 0; dd < 8; dd++) op[dd] = outacc[dd] * inv;
}

// ---------------- elementwise helpers ----------------
__global__ void add_seg_kernel(float* __restrict__ X, const float* __restrict__ seg)
{
    long n = (long)BATCH * SEQ * EMB;
    for (long idx = (long)blockIdx.x * blockDim.x + threadIdx.x; idx < n;
         idx += (long)gridDim.x * blockDim.x) {
        long r = idx / EMB;
        int col = (int)(idx - r * EMB);
        int t = (int)((r % SEQ) / NW);
        X[idx] += seg[(long)t * EMB + col];
    }
}

__global__ void bcast_lat_kernel(const float* __restrict__ lat, float* __restrict__ LAT)
{
    long n = (long)BATCH * NLAT * EMB;
    for (long idx = (long)blockIdx.x * blockDim.x + threadIdx.x; idx < n;
         idx += (long)gridDim.x * blockDim.x) {
        LAT[idx] = lat[idx % ((long)NLAT * EMB)];
    }
}

// ---------------- host orchestration ----------------
static float* symaddr(const void* symbol) {
    void* p = 0;
    cudaGetSymbolAddress(&p, symbol);
    return (float*)p;
}

extern "C" void kernel_launch(void* const* d_in, const int* in_sizes, int n_in,
                              void* d_out, int out_size)
{
    (void)in_sizes; (void)n_in; (void)out_size;
    const float* x        = (const float*)d_in[0];
    const float* g_norm_s = (const float*)d_in[1];
    const float* g_norm_b = (const float*)d_in[2];
    const float* g_wq     = (const float*)d_in[3];
    const float* g_wkv    = (const float*)d_in[4];
    const float* g_wo     = (const float*)d_in[5];
    const float* seg_emb  = (const float*)d_in[6];
    const float* latents  = (const float*)d_in[7];
    const float* a_nm_s   = (const float*)d_in[8];
    const float* a_nm_b   = (const float*)d_in[9];
    const float* a_nl_s   = (const float*)d_in[10];
    const float* a_nl_b   = (const float*)d_in[11];
    const float* a_wq     = (const float*)d_in[12];
    const float* a_wkv    = (const float*)d_in[13];
    const float* a_wo     = (const float*)d_in[14];
    const float* f_n_s    = (const float*)d_in[15];
    const float* f_n_b    = (const float*)d_in[16];
    const float* f_w1     = (const float*)d_in[17];
    const float* f_w2     = (const float*)d_in[18];
    const float* out_n_s  = (const float*)d_in[19];
    const float* out_n_b  = (const float*)d_in[20];
    float* out = (float*)d_out;

    float* X1  = symaddr(g_X1);
    float* Q   = symaddr(g_Q);
    float* KV  = symaddr(g_KV);
    float* AO  = symaddr(g_AO);
    float* X   = symaddr(g_X);
    float* LAT = symaddr(g_LAT);
    float* LM  = symaddr(g_LM);
    float* QL  = symaddr(g_QL);
    float* KVA = symaddr(g_KVA);
    float* O   = symaddr(g_O);
    float* H   = symaddr(g_H);

    const int MSEQ = BATCH * SEQ;    // 18816 (147*128)
    const int MLAT = BATCH * NLAT;   // 4096  (32*128)

    // ---- stage A ----
    ln_kernel<<<MSEQ, 256>>>(x, g_norm_s, g_norm_b, X1);
    sgemm128<<<dim3(INNER/128, MSEQ/128), 256>>>(X1, g_wq,  Q,  MSEQ, INNER,  EMB, 0, 0, 1, 1, 0);
    sgemm128<<<dim3(1024/128,  MSEQ/128), 256>>>(X1, g_wkv, KV, MSEQ, 1024,   EMB, 0, 0, 1, 1, 0);
    attn_local_kernel<<<BATCH*HEADS*TT, 256>>>(Q, KV, AO);
    sgemm128<<<dim3(EMB/128, MSEQ/128), 256>>>(AO, g_wo, X, MSEQ, EMB, INNER, 0, 0, 1, 1, 0);
    add_seg_kernel<<<4096, 256>>>(X, seg_emb);
    bcast_lat_kernel<<<2048, 256>>>(latents, LAT);

    // ---- depth loop ----
    for (int l = 0; l < NDEPTH; l++) {
        const float* wq  = a_wq  + (long)l * EMB * INNER;
        const float* wkv = a_wkv + (long)l * EMB * 2 * INNER;
        const float* wo  = a_wo  + (long)l * INNER * EMB;
        const float* w1  = f_w1  + (long)l * EMB * FFD;
        const float* w2  = f_w2  + (long)l * FFD * EMB;

        ln_kernel<<<MSEQ, 256>>>(X,   a_nm_s + l*EMB, a_nm_b + l*EMB, X1);  // xm
        ln_kernel<<<MLAT, 256>>>(LAT, a_nl_s + l*EMB, a_nl_b + l*EMB, LM);  // lm

        sgemm128<<<dim3(INNER/128, MLAT/128), 256>>>(LM, wq, QL, MLAT, INNER, EMB, 0, 0, 1, 1, 0);
        // concat([xm, lm]) @ wkv  ->  KVA rows [0,1176) and [1176,1432) per batch
        sgemm128<<<dim3(1024/128, MSEQ/128), 256>>>(X1, wkv, KVA, MSEQ, 1024, EMB, 0, 0, SEQ,  LKV, 0);
        sgemm128<<<dim3(1024/128, MLAT/128), 256>>>(LM, wkv, KVA, MLAT, 1024, EMB, 0, 0, NLAT, LKV, SEQ);

        attn_latent_kernel<<<BATCH*HEADS*(NLAT/32), 256>>>(QL, KVA, O);

        // lat = lat + o @ wo
        sgemm128<<<dim3(EMB/128, MLAT/128), 256>>>(O, wo, LAT, MLAT, EMB, INNER, LAT, 0, 1, 1, 0);

        // ff
        ln_kernel<<<MLAT, 256>>>(LAT, f_n_s + l*EMB, f_n_b + l*EMB, LM);
        sgemm128<<<dim3(FFD/128, MLAT/128), 256>>>(LM, w1, H, MLAT, FFD, EMB, 0, 1, 1, 1, 0);   // gelu
        sgemm128<<<dim3(EMB/128, MLAT/128), 256>>>(H, w2, LAT, MLAT, EMB, FFD, LAT, 0, 1, 1, 0);
    }

    // ---- final norm ----
    ln_kernel<<<MLAT, 256>>>(LAT, out_n_s, out_n_b, out);
}

// round 3
// speedup vs baseline: 2.4831x; 2.4831x over previous
#include <cuda_runtime.h>
#include <cuda_bf16.h>
#include <math.h>
#include <stdint.h>

// ---------------- problem constants ----------------
#define BATCH 16
#define TT    24
#define NW    49
#define SEQ   (TT*NW)        // 1176
#define EMB   2048
#define HEADS 8
#define DHEAD 64
#define INNER 512
#define NLAT  256
#define LKV   (SEQ + NLAT)   // 1432
#define FFD   8192
#define NDEPTH 3
#define EPSV  1e-5f
#define ATT_SCALE 0.125f

// ---------------- scratch (device globals) ----------------
__device__ float g_Q  [BATCH*SEQ*INNER];
__device__ float g_KV [BATCH*SEQ*2*INNER];
__device__ float g_AO [BATCH*SEQ*INNER];
__device__ float g_X  [BATCH*SEQ*EMB];
__device__ float g_LAT[BATCH*NLAT*EMB];
__device__ float g_QL [BATCH*NLAT*INNER];
__device__ float g_KVA[BATCH*LKV*2*INNER];
__device__ float g_O  [BATCH*NLAT*INNER];
// bf16 split operands
__device__ __nv_bfloat16 g_Ahi[BATCH*SEQ*EMB];   // seq-sized A (also reused for H)
__device__ __nv_bfloat16 g_Alo[BATCH*SEQ*EMB];
__device__ __nv_bfloat16 g_Lhi[BATCH*NLAT*EMB];  // latent-sized A
__device__ __nv_bfloat16 g_Llo[BATCH*NLAT*EMB];
__device__ __nv_bfloat16 g_Bhi[FFD*EMB];
__device__ __nv_bfloat16 g_Blo[FFD*EMB];

// ---------------- HMMA GEMM (mma.sync m16n8k16 bf16, 3-term split) ----------------
// C[M,N] = op(Ahi@B^T + Ahi@Blo^T + Alo@Bhi^T). A: [M,K] K-major, B: [N,K] K-major.
// If Chi != 0: write bf16 hi/lo split output (after gelu). Else fp32 (+addsrc).
// Output row remap: gr -> (gr/in_rpb)*out_rpb + out_off + gr%in_rpb.
#define PITCHB 80               // bytes per 32-k row (40 bf16, conflict-free pitch)
#define ASTG   (128*PITCHB)     // 10240 bytes per operand tile
#define STAGE  (4*ASTG)         // 40960 per stage (Ah,Al,Bh,Bl)
#define GEMM_SMEM (2*STAGE)     // 81920

#define MMA(d, a, b) \
  asm volatile("mma.sync.aligned.m16n8k16.row.col.f32.bf16.bf16.f32 " \
    "{%0,%1,%2,%3}, {%4,%5,%6,%7}, {%8,%9}, {%0,%1,%2,%3};" \
    : "+f"((d)[0]), "+f"((d)[1]), "+f"((d)[2]), "+f"((d)[3]) \
    : "r"((a)[0]), "r"((a)[1]), "r"((a)[2]), "r"((a)[3]), "r"((b)[0]), "r"((b)[1]))

__global__ void __launch_bounds__(256, 1) gemm_hmma(
    const __nv_bfloat16* __restrict__ Ahi, const __nv_bfloat16* __restrict__ Alo,
    const __nv_bfloat16* __restrict__ Bhi, const __nv_bfloat16* __restrict__ Blo,
    float* __restrict__ C,
    __nv_bfloat16* __restrict__ Chi, __nv_bfloat16* __restrict__ Clo,
    int M, int N, int K,
    const float* __restrict__ addsrc, int do_gelu,
    int in_rpb, int out_rpb, int out_off)
{
    extern __shared__ char sm[];
    const int tid  = threadIdx.x;
    const int lane = tid & 31, wid = tid >> 5;
    const int wr = wid >> 2, wc = wid & 3;
    const int gid = lane >> 2, tig = lane & 3;
    const int row0 = blockIdx.y * 128, col0 = blockIdx.x * 128;

    // global->smem staging: thread covers half a 32-k row (16 bf16 = 32B)
    const int ldrow  = tid >> 1;
    const int ldhalf = (tid & 1) * 16;
    const uint32_t sto = (uint32_t)ldrow * PITCHB + (tid & 1) * 32;
    const size_t abase = (size_t)(row0 + ldrow) * K + ldhalf;
    const size_t bbase = (size_t)(col0 + ldrow) * K + ldhalf;

    float acc[4][4][4];
    #pragma unroll
    for (int i = 0; i < 4; i++)
        #pragma unroll
        for (int j = 0; j < 4; j++)
            #pragma unroll
            for (int k = 0; k < 4; k++) acc[i][j][k] = 0.f;

    uint4 rah0, rah1, ral0, ral1, rbh0, rbh1, rbl0, rbl1;

#define GLOAD(kc) do { \
    size_t ao = abase + (kc); \
    rah0 = *(const uint4*)(Ahi + ao); rah1 = *(const uint4*)(Ahi + ao + 8); \
    ral0 = *(const uint4*)(Alo + ao); ral1 = *(const uint4*)(Alo + ao + 8); \
    size_t bo = bbase + (kc); \
    rbh0 = *(const uint4*)(Bhi + bo); rbh1 = *(const uint4*)(Bhi + bo + 8); \
    rbl0 = *(const uint4*)(Blo + bo); rbl1 = *(const uint4*)(Blo + bo + 8); \
  } while (0)

#define SSTORE(p) do { \
    char* b = sm + (p) * STAGE + sto; \
    *(uint4*)(b)              = rah0; *(uint4*)(b + 16)            = rah1; \
    *(uint4*)(b + ASTG)       = ral0; *(uint4*)(b + ASTG + 16)     = ral1; \
    *(uint4*)(b + 2*ASTG)     = rbh0; *(uint4*)(b + 2*ASTG + 16)   = rbh1; \
    *(uint4*)(b + 3*ASTG)     = rbl0; *(uint4*)(b + 3*ASTG + 16)   = rbl1; \
  } while (0)

    const int nch = K / 32;
    GLOAD(0);
    SSTORE(0);

    for (int i = 0; i < nch; i++) {
        __syncthreads();
        if (i + 1 < nch) GLOAD((i + 1) * 32);

        const char* bs = sm + (i & 1) * STAGE;
        #pragma unroll
        for (int ks = 0; ks < 2; ks++) {
            const int kb = ks * 32;
            uint32_t ah[4][4], al[4][4], bh[4][2], bl[4][2];
            #pragma unroll
            for (int mi = 0; mi < 4; mi++) {
                const char* p = bs + (uint32_t)((wr*64 + mi*16 + gid) * PITCHB + kb + tig*4);
                ah[mi][0] = *(const uint32_t*)(p);
                ah[mi][1] = *(const uint32_t*)(p + 8*PITCHB);
                ah[mi][2] = *(const uint32_t*)(p + 16);
                ah[mi][3] = *(const uint32_t*)(p + 8*PITCHB + 16);
                al[mi][0] = *(const uint32_t*)(p + ASTG);
                al[mi][1] = *(const uint32_t*)(p + ASTG + 8*PITCHB);
                al[mi][2] = *(const uint32_t*)(p + ASTG + 16);
                al[mi][3] = *(const uint32_t*)(p + ASTG + 8*PITCHB + 16);
            }
            #pragma unroll
            for (int ni = 0; ni < 4; ni++) {
                const char* p = bs + 2*ASTG + (uint32_t)((wc*32 + ni*8 + gid) * PITCHB + kb + tig*4);
                bh[ni][0] = *(const uint32_t*)(p);
                bh[ni][1] = *(const uint32_t*)(p + 16);
                bl[ni][0] = *(const uint32_t*)(p + ASTG);
                bl[ni][1] = *(const uint32_t*)(p + ASTG + 16);
            }
            #pragma unroll
            for (int mi = 0; mi < 4; mi++)
                #pragma unroll
                for (int ni = 0; ni < 4; ni++) {
                    MMA(acc[mi][ni], ah[mi], bh[ni]);
                    MMA(acc[mi][ni], ah[mi], bl[ni]);
                    MMA(acc[mi][ni], al[mi], bh[ni]);
                }
        }
        if (i + 1 < nch) SSTORE((i + 1) & 1);
    }

    // ---- epilogue ----
    #pragma unroll
    for (int mi = 0; mi < 4; mi++) {
        #pragma unroll
        for (int ci = 0; ci < 2; ci++) {
            long gr = row0 + wr*64 + mi*16 + ci*8 + gid;
            long bb2 = gr / in_rpb;
            long orow = bb2 * (long)out_rpb + out_off + (gr - bb2 * (long)in_rpb);
            #pragma unroll
            for (int ni = 0; ni < 4; ni++) {
                int col = col0 + wc*32 + ni*8 + tig*2;
                float v0 = acc[mi][ni][ci*2 + 0];
                float v1 = acc[mi][ni][ci*2 + 1];
                if (do_gelu) {
                    v0 = 0.5f * v0 * (1.0f + erff(v0 * 0.70710678118654752f));
                    v1 = 0.5f * v1 * (1.0f + erff(v1 * 0.70710678118654752f));
                }
                long off = orow * (long)N + col;
                if (Chi) {
                    __nv_bfloat16 h0 = __float2bfloat16(v0);
                    __nv_bfloat16 h1 = __float2bfloat16(v1);
                    __nv_bfloat16 l0 = __float2bfloat16(v0 - __bfloat162float(h0));
                    __nv_bfloat16 l1 = __float2bfloat16(v1 - __bfloat162float(h1));
                    *(__nv_bfloat162*)(Chi + off) = __halves2bfloat162(h0, h1);
                    *(__nv_bfloat162*)(Clo + off) = __halves2bfloat162(l0, l1);
                } else {
                    if (addsrc) {
                        float2 d = *(const float2*)(addsrc + off);
                        v0 += d.x; v1 += d.y;
                    }
                    *(float2*)(C + off) = make_float2(v0, v1);
                }
            }
        }
    }
}

// ---------------- LayerNorm -> fp32 out ----------------
__device__ __forceinline__ void ln_stats(const float4& va, const float4& vb,
                                         float& mean, float& rstd, int tid)
{
    float sum = va.x+va.y+va.z+va.w + vb.x+vb.y+vb.z+vb.w;
    float sq  = va.x*va.x+va.y*va.y+va.z*va.z+va.w*va.w
              + vb.x*vb.x+vb.y*vb.y+vb.z*vb.z+vb.w*vb.w;
    #pragma unroll
    for (int o = 16; o > 0; o >>= 1) {
        sum += __shfl_down_sync(0xffffffffu, sum, o);
        sq  += __shfl_down_sync(0xffffffffu, sq, o);
    }
    __shared__ float rs[16];
    __shared__ float mbv[2];
    int w = tid >> 5, lanei = tid & 31;
    if (!lanei) { rs[w] = sum; rs[8 + w] = sq; }
    __syncthreads();
    if (tid == 0) {
        float s = 0.f, q = 0.f;
        #pragma unroll
        for (int i = 0; i < 8; i++) { s += rs[i]; q += rs[8 + i]; }
        float m = s * (1.0f / EMB);
        float v = q * (1.0f / EMB) - m * m;
        mbv[0] = m; mbv[1] = rsqrtf(v + EPSV);
    }
    __syncthreads();
    mean = mbv[0]; rstd = mbv[1];
}

__global__ void __launch_bounds__(256) ln_kernel(
    const float* __restrict__ in, const float* __restrict__ sc,
    const float* __restrict__ bi, float* __restrict__ out)
{
    long r = blockIdx.x;
    const float* x = in + r * (long)EMB;
    int tid = threadIdx.x;
    float4 va = ((const float4*)x)[tid];
    float4 vb = ((const float4*)x)[tid + 256];
    float mean, rstd;
    ln_stats(va, vb, mean, rstd, tid);

    float4 sa = ((const float4*)sc)[tid], sb = ((const float4*)sc)[tid + 256];
    float4 ba = ((const float4*)bi)[tid], bb = ((const float4*)bi)[tid + 256];
    float4 oa, ob;
    oa.x = (va.x-mean)*rstd*sa.x + ba.x;  oa.y = (va.y-mean)*rstd*sa.y + ba.y;
    oa.z = (va.z-mean)*rstd*sa.z + ba.z;  oa.w = (va.w-mean)*rstd*sa.w + ba.w;
    ob.x = (vb.x-mean)*rstd*sb.x + bb.x;  ob.y = (vb.y-mean)*rstd*sb.y + bb.y;
    ob.z = (vb.z-mean)*rstd*sb.z + bb.z;  ob.w = (vb.w-mean)*rstd*sb.w + bb.w;
    float* y = out + r * (long)EMB;
    ((float4*)y)[tid] = oa;
    ((float4*)y)[tid + 256] = ob;
}

// ---------------- LayerNorm -> bf16 hi/lo split ----------------
__global__ void __launch_bounds__(256) ln_split(
    const float* __restrict__ in, const float* __restrict__ sc,
    const float* __restrict__ bi,
    __nv_bfloat16* __restrict__ hi, __nv_bfloat16* __restrict__ lo)
{
    long r = blockIdx.x;
    const float* x = in + r * (long)EMB;
    int tid = threadIdx.x;
    float4 va = ((const float4*)x)[tid];
    float4 vb = ((const float4*)x)[tid + 256];
    float mean, rstd;
    ln_stats(va, vb, mean, rstd, tid);

    float4 sa = ((const float4*)sc)[tid], sb = ((const float4*)sc)[tid + 256];
    float4 ba = ((const float4*)bi)[tid], bb = ((const float4*)bi)[tid + 256];
    float y[8];
    y[0]=(va.x-mean)*rstd*sa.x+ba.x; y[1]=(va.y-mean)*rstd*sa.y+ba.y;
    y[2]=(va.z-mean)*rstd*sa.z+ba.z; y[3]=(va.w-mean)*rstd*sa.w+ba.w;
    y[4]=(vb.x-mean)*rstd*sb.x+bb.x; y[5]=(vb.y-mean)*rstd*sb.y+bb.y;
    y[6]=(vb.z-mean)*rstd*sb.z+bb.z; y[7]=(vb.w-mean)*rstd*sb.w+bb.w;

    __nv_bfloat162* hp = (__nv_bfloat162*)(hi + r * (long)EMB);
    __nv_bfloat162* lp = (__nv_bfloat162*)(lo + r * (long)EMB);
    #pragma unroll
    for (int g = 0; g < 2; g++) {
        int base = g ? (tid + 256) * 4 : tid * 4;
        #pragma unroll
        for (int j = 0; j < 2; j++) {
            float v0 = y[g*4 + j*2], v1 = y[g*4 + j*2 + 1];
            __nv_bfloat16 h0 = __float2bfloat16(v0), h1 = __float2bfloat16(v1);
            __nv_bfloat16 l0 = __float2bfloat16(v0 - __bfloat162float(h0));
            __nv_bfloat16 l1 = __float2bfloat16(v1 - __bfloat162float(h1));
            hp[base/2 + j] = __halves2bfloat162(h0, h1);
            lp[base/2 + j] = __halves2bfloat162(l0, l1);
        }
    }
}

// ---------------- conversions ----------------
__global__ void cvt_act(const float* __restrict__ in,
                        __nv_bfloat16* __restrict__ hi, __nv_bfloat16* __restrict__ lo, long n4)
{
    for (long i = (long)blockIdx.x * blockDim.x + threadIdx.x; i < n4;
         i += (long)gridDim.x * blockDim.x) {
        float4 v = ((const float4*)in)[i];
        __nv_bfloat16 h0 = __float2bfloat16(v.x), h1 = __float2bfloat16(v.y);
        __nv_bfloat16 h2 = __float2bfloat16(v.z), h3 = __float2bfloat16(v.w);
        __nv_bfloat16 l0 = __float2bfloat16(v.x - __bfloat162float(h0));
        __nv_bfloat16 l1 = __float2bfloat16(v.y - __bfloat162float(h1));
        __nv_bfloat16 l2 = __float2bfloat16(v.z - __bfloat162float(h2));
        __nv_bfloat16 l3 = __float2bfloat16(v.w - __bfloat162float(h3));
        __nv_bfloat162* hp = (__nv_bfloat162*)(hi + 4 * i);
        __nv_bfloat162* lp = (__nv_bfloat162*)(lo + 4 * i);
        hp[0] = __halves2bfloat162(h0, h1); hp[1] = __halves2bfloat162(h2, h3);
        lp[0] = __halves2bfloat162(l0, l1); lp[1] = __halves2bfloat162(l2, l3);
    }
}

// W [K,N] fp32 -> Bhi/Blo [N,K] bf16 (transpose + split)
__global__ void __launch_bounds__(256) cvt_wT(const float* __restrict__ W,
    __nv_bfloat16* __restrict__ bhi, __nv_bfloat16* __restrict__ blo, int K, int N)
{
    __shared__ float t[32][33];
    int n0 = blockIdx.x * 32, k0 = blockIdx.y * 32;
    int tx = threadIdx.x & 31, ty = threadIdx.x >> 5;
    #pragma unroll
    for (int j = 0; j < 32; j += 8)
        t[ty + j][tx] = W[(long)(k0 + ty + j) * N + n0 + tx];
    __syncthreads();
    #pragma unroll
    for (int j = 0; j < 32; j += 8) {
        int n = n0 + ty + j, k = k0 + tx;
        float v = t[tx][ty + j];
        __nv_bfloat16 h = __float2bfloat16(v);
        bhi[(long)n * K + k] = h;
        blo[(long)n * K + k] = __float2bfloat16(v - __bfloat162float(h));
    }
}

// ---------------- local attention (one block per (b,h,t), 49x49) ----------------
__global__ void __launch_bounds__(256) attn_local_kernel(
    const float* __restrict__ Q, const float* __restrict__ KV, float* __restrict__ O)
{
    __shared__ float qsT[DHEAD][NW];
    __shared__ float ksT[DHEAD][NW];
    __shared__ float sim[NW * NW];

    int g = blockIdx.x;
    int t = g % TT;
    int h = (g / TT) % HEADS;
    int b = g / (TT * HEADS);
    long base = (long)b * SEQ + (long)t * NW;
    int tid = threadIdx.x;

    for (int e = tid; e < NW * DHEAD; e += 256) {
        int i = e >> 6, d = e & 63;
        qsT[d][i] = Q [(base + i) * INNER     + h * DHEAD + d] * ATT_SCALE;
        ksT[d][i] = KV[(base + i) * (2*INNER) + h * DHEAD + d];
    }
    __syncthreads();

    for (int p = tid; p < NW * NW; p += 256) {
        int i = p / NW, j = p % NW;
        float s = 0.f;
        #pragma unroll
        for (int d = 0; d < DHEAD; d++) s += qsT[d][i] * ksT[d][j];
        sim[p] = s;
    }
    __syncthreads();

    if (tid < NW) {
        float m = -1e30f;
        for (int j = 0; j < NW; j++) m = fmaxf(m, sim[tid * NW + j]);
        float sum = 0.f;
        for (int j = 0; j < NW; j++) {
            float e = expf(sim[tid * NW + j] - m);
            sim[tid * NW + j] = e;
            sum += e;
        }
        float inv = 1.0f / sum;
        for (int j = 0; j < NW; j++) sim[tid * NW + j] *= inv;
    }
    __syncthreads();

    for (int e = tid; e < NW * DHEAD; e += 256) {
        int j = e >> 6, d = e & 63;
        qsT[d][j] = KV[(base + j) * (2*INNER) + INNER + h * DHEAD + d];
    }
    __syncthreads();

    for (int o = tid; o < NW * DHEAD; o += 256) {
        int i = o >> 6, d = o & 63;
        float acc = 0.f;
        for (int j = 0; j < NW; j++) acc += sim[i * NW + j] * qsT[d][j];
        O[(base + i) * INNER + h * DHEAD + d] = acc;
    }
}

// ---------------- latent cross-attention (online softmax) ----------------
__global__ void __launch_bounds__(256) attn_latent_kernel(
    const float* __restrict__ QL, const float* __restrict__ KVA, float* __restrict__ O)
{
    __shared__ float qsT[DHEAD][32];
    __shared__ float ksT[DHEAD][32];
    __shared__ float vs [32][DHEAD];

    int blk = blockIdx.x;
    int qt = blk & 7;
    int h  = (blk >> 3) & 7;
    int b  = blk >> 6;
    int q0 = qt * 32;
    int tid = threadIdx.x;
    int r = tid >> 3;
    int c = tid & 7;
    int d0 = c * 8;

    for (int e = tid; e < 32 * DHEAD; e += 256) {
        int i = e >> 6, d = e & 63;
        qsT[d][i] = QL[((long)b * NLAT + q0 + i) * INNER + h * DHEAD + d] * ATT_SCALE;
    }

    float outacc[8];
    #pragma unroll
    for (int dd = 0; dd < 8; dd++) outacc[dd] = 0.f;
    float rowmax = -1e30f, rowsum = 0.f;
    int lanebase = (tid & 31) & ~7;
    __syncthreads();

    for (int j0 = 0; j0 < LKV; j0 += 32) {
        int jn = LKV - j0; if (jn > 32) jn = 32;
        for (int e = tid; e < 32 * DHEAD; e += 256) {
            int j = e >> 6, d = e & 63;
            if (j < jn) {
                long row = (long)b * LKV + j0 + j;
                ksT[d][j] = KVA[row * (2*INNER)         + h * DHEAD + d];
                vs [j][d] = KVA[row * (2*INNER) + INNER + h * DHEAD + d];
            } else {
                ksT[d][j] = 0.f;
                vs [j][d] = 0.f;
            }
        }
        __syncthreads();

        float s[4];
        #pragma unroll
        for (int jj = 0; jj < 4; jj++) {
            int j = c * 4 + jj;
            float acc = 0.f;
            #pragma unroll
            for (int d = 0; d < DHEAD; d++) acc += qsT[d][r] * ksT[d][j];
            s[jj] = (j < jn) ? acc : -1e30f;
        }
        float cm = fmaxf(fmaxf(s[0], s[1]), fmaxf(s[2], s[3]));
        cm = fmaxf(cm, __shfl_xor_sync(0xffffffffu, cm, 1));
        cm = fmaxf(cm, __shfl_xor_sync(0xffffffffu, cm, 2));
        cm = fmaxf(cm, __shfl_xor_sync(0xffffffffu, cm, 4));
        float nm = fmaxf(rowmax, cm);
        float corr = expf(rowmax - nm);
        float p[4], ps = 0.f;
        #pragma unroll
        for (int jj = 0; jj < 4; jj++) { p[jj] = expf(s[jj] - nm); ps += p[jj]; }
        ps += __shfl_xor_sync(0xffffffffu, ps, 1);
        ps += __shfl_xor_sync(0xffffffffu, ps, 2);
        ps += __shfl_xor_sync(0xffffffffu, ps, 4);
        rowsum = rowsum * corr + ps;
        rowmax = nm;
        #pragma unroll
        for (int dd = 0; dd < 8; dd++) outacc[dd] *= corr;

        #pragma unroll
        for (int jc = 0; jc < 8; jc++) {
            #pragma unroll
            for (int jj = 0; jj < 4; jj++) {
                float pj = __shfl_sync(0xffffffffu, p[jj], lanebase + jc);
                int j = jc * 4 + jj;
                #pragma unroll
                for (int dd = 0; dd < 8; dd++)
                    outacc[dd] += pj * vs[j][d0 + dd];
            }
        }
        __syncthreads();
    }

    float inv = 1.0f / rowsum;
    float* op = O + ((long)b * NLAT + q0 + r) * INNER + h * DHEAD + d0;
    #pragma unroll
    for (int dd = 0; dd < 8; dd++) op[dd] = outacc[dd] * inv;
}

// ---------------- elementwise helpers ----------------
__global__ void add_seg_kernel(float* __restrict__ X, const float* __restrict__ seg)
{
    long n = (long)BATCH * SEQ * EMB;
    for (long idx = (long)blockIdx.x * blockDim.x + threadIdx.x; idx < n;
         idx += (long)gridDim.x * blockDim.x) {
        long r = idx / EMB;
        int col = (int)(idx - r * EMB);
        int t = (int)((r % SEQ) / NW);
        X[idx] += seg[(long)t * EMB + col];
    }
}

__global__ void bcast_lat_kernel(const float* __restrict__ lat, float* __restrict__ LAT)
{
    long n = (long)BATCH * NLAT * EMB;
    for (long idx = (long)blockIdx.x * blockDim.x + threadIdx.x; idx < n;
         idx += (long)gridDim.x * blockDim.x) {
        LAT[idx] = lat[idx % ((long)NLAT * EMB)];
    }
}

// ---------------- host ----------------
static float* symaddr_f(const void* s) { void* p = 0; cudaGetSymbolAddress(&p, s); return (float*)p; }
static __nv_bfloat16* symaddr_b(const void* s) { void* p = 0; cudaGetSymbolAddress(&p, s); return (__nv_bfloat16*)p; }

static void run_gemm(const __nv_bfloat16* Ah, const __nv_bfloat16* Al,
                     const __nv_bfloat16* Bh, const __nv_bfloat16* Bl,
                     float* C, __nv_bfloat16* Chi, __nv_bfloat16* Clo,
                     int M, int N, int K,
                     const float* addsrc, int do_gelu,
                     int in_rpb, int out_rpb, int out_off)
{
    gemm_hmma<<<dim3(N / 128, M / 128), 256, GEMM_SMEM>>>(
        Ah, Al, Bh, Bl, C, Chi, Clo, M, N, K, addsrc, do_gelu, in_rpb, out_rpb, out_off);
}

extern "C" void kernel_launch(void* const* d_in, const int* in_sizes, int n_in,
                              void* d_out, int out_size)
{
    (void)in_sizes; (void)n_in; (void)out_size;
    const float* x        = (const float*)d_in[0];
    const float* g_norm_s = (const float*)d_in[1];
    const float* g_norm_b = (const float*)d_in[2];
    const float* g_wq     = (const float*)d_in[3];
    const float* g_wkv    = (const float*)d_in[4];
    const float* g_wo     = (const float*)d_in[5];
    const float* seg_emb  = (const float*)d_in[6];
    const float* latents  = (const float*)d_in[7];
    const float* a_nm_s   = (const float*)d_in[8];
    const float* a_nm_b   = (const float*)d_in[9];
    const float* a_nl_s   = (const float*)d_in[10];
    const float* a_nl_b   = (const float*)d_in[11];
    const float* a_wq     = (const float*)d_in[12];
    const float* a_wkv    = (const float*)d_in[13];
    const float* a_wo     = (const float*)d_in[14];
    const float* f_n_s    = (const float*)d_in[15];
    const float* f_n_b    = (const float*)d_in[16];
    const float* f_w1     = (const float*)d_in[17];
    const float* f_w2     = (const float*)d_in[18];
    const float* out_n_s  = (const float*)d_in[19];
    const float* out_n_b  = (const float*)d_in[20];
    float* out = (float*)d_out;

    float* Q   = symaddr_f(g_Q);
    float* KV  = symaddr_f(g_KV);
    float* AO  = symaddr_f(g_AO);
    float* X   = symaddr_f(g_X);
    float* LAT = symaddr_f(g_LAT);
    float* QL  = symaddr_f(g_QL);
    float* KVA = symaddr_f(g_KVA);
    float* O   = symaddr_f(g_O);
    __nv_bfloat16* Ahi = symaddr_b(g_Ahi);
    __nv_bfloat16* Alo = symaddr_b(g_Alo);
    __nv_bfloat16* Lhi = symaddr_b(g_Lhi);
    __nv_bfloat16* Llo = symaddr_b(g_Llo);
    __nv_bfloat16* Bhi = symaddr_b(g_Bhi);
    __nv_bfloat16* Blo = symaddr_b(g_Blo);

    cudaFuncSetAttribute(gemm_hmma, cudaFuncAttributeMaxDynamicSharedMemorySize, GEMM_SMEM);

    const int MSEQ = BATCH * SEQ;    // 18816 = 147*128
    const int MLAT = BATCH * NLAT;   // 4096

    // ---- stage A ----
    ln_split<<<MSEQ, 256>>>(x, g_norm_s, g_norm_b, Ahi, Alo);
    cvt_wT<<<dim3(INNER/32, EMB/32), 256>>>(g_wq, Bhi, Blo, EMB, INNER);
    run_gemm(Ahi, Alo, Bhi, Blo, Q, 0, 0, MSEQ, INNER, EMB, 0, 0, 1, 1, 0);
    cvt_wT<<<dim3(1024/32, EMB/32), 256>>>(g_wkv, Bhi, Blo, EMB, 1024);
    run_gemm(Ahi, Alo, Bhi, Blo, KV, 0, 0, MSEQ, 1024, EMB, 0, 0, 1, 1, 0);
    attn_local_kernel<<<BATCH*HEADS*TT, 256>>>(Q, KV, AO);
    cvt_act<<<4096, 256>>>(AO, Ahi, Alo, (long)MSEQ * INNER / 4);
    cvt_wT<<<dim3(EMB/32, INNER/32), 256>>>(g_wo, Bhi, Blo, INNER, EMB);
    run_gemm(Ahi, Alo, Bhi, Blo, X, 0, 0, MSEQ, EMB, INNER, 0, 0, 1, 1, 0);
    add_seg_kernel<<<4096, 256>>>(X, seg_emb);
    bcast_lat_kernel<<<2048, 256>>>(latents, LAT);

    // ---- depth loop ----
    for (int l = 0; l < NDEPTH; l++) {
        const float* wq  = a_wq  + (long)l * EMB * INNER;
        const float* wkv = a_wkv + (long)l * EMB * 2 * INNER;
        const float* wo  = a_wo  + (long)l * INNER * EMB;
        const float* w1  = f_w1  + (long)l * EMB * FFD;
        const float* w2  = f_w2  + (long)l * FFD * EMB;

        ln_split<<<MSEQ, 256>>>(X,   a_nm_s + l*EMB, a_nm_b + l*EMB, Ahi, Alo);  // xm
        ln_split<<<MLAT, 256>>>(LAT, a_nl_s + l*EMB, a_nl_b + l*EMB, Lhi, Llo);  // lm

        cvt_wT<<<dim3(INNER/32, EMB/32), 256>>>(wq, Bhi, Blo, EMB, INNER);
        run_gemm(Lhi, Llo, Bhi, Blo, QL, 0, 0, MLAT, INNER, EMB, 0, 0, 1, 1, 0);
        cvt_wT<<<dim3(1024/32, EMB/32), 256>>>(wkv, Bhi, Blo, EMB, 1024);
        run_gemm(Lhi, Llo, Bhi, Blo, KVA, 0, 0, MLAT, 1024, EMB, 0, 0, NLAT, LKV, SEQ);
        run_gemm(Ahi, Alo, Bhi, Blo, KVA, 0, 0, MSEQ, 1024, EMB, 0, 0, SEQ,  LKV, 0);

        attn_latent_kernel<<<BATCH*HEADS*(NLAT/32), 256>>>(QL, KVA, O);

        cvt_act<<<2048, 256>>>(O, Lhi, Llo, (long)MLAT * INNER / 4);
        cvt_wT<<<dim3(EMB/32, INNER/32), 256>>>(wo, Bhi, Blo, INNER, EMB);
        run_gemm(Lhi, Llo, Bhi, Blo, LAT, 0, 0, MLAT, EMB, INNER, LAT, 0, 1, 1, 0);

        ln_split<<<MLAT, 256>>>(LAT, f_n_s + l*EMB, f_n_b + l*EMB, Lhi, Llo);
        cvt_wT<<<dim3(FFD/32, EMB/32), 256>>>(w1, Bhi, Blo, EMB, FFD);
        // FF1: gelu + bf16-split output into Ahi/Alo (xm split no longer needed)
        run_gemm(Lhi, Llo, Bhi, Blo, 0, Ahi, Alo, MLAT, FFD, EMB, 0, 1, 1, 1, 0);
        cvt_wT<<<dim3(EMB/32, FFD/32), 256>>>(w2, Bhi, Blo, FFD, EMB);
        run_gemm(Ahi, Alo, Bhi, Blo, LAT, 0, 0, MLAT, EMB, FFD, LAT, 0, 1, 1, 0);
    }

    ln_kernel<<<MLAT, 256>>>(LAT, out_n_s, out_n_b, out);
}